// round 12
// baseline (speedup 1.0000x reference)
#include <cuda_runtime.h>

// CrossAttMultiplexer collapses analytically:
//   q = x*WQ (outer product with scalar), k = s*WK  ->  scores rank-1:
//   scores[n,i,j] = (WQ.WK)/sqrt(d) * x[n,i] * s[n,j]
//   alpha = softmax(scores, axis=-1)
//   out[n,i] = v[n,i] * sum_j alpha[n,i,j] = v[n,i] * 1 = s[n,i] * WV[0]
// The attention cancels entirely; the op is an elementwise scale of s.
// Mandatory traffic: read s (6.29MB) + write out (6.29MB) = 12.6MB.
//
// R12: REPLICATION of R11 (e2e 6.656, best kernel dur 5.28us, best HBM
// 1192GB/s). The asymmetric cache policy is the candidate causal effect:
//   - DEFAULT loads: s is re-read every timed replay -> keep L2-resident
//   - STREAMING stores (__stcs): out has zero read reuse -> evict-first,
//     the write stream doesn't displace the read set in LTS.
// Unlike the R5 outlier (e2e-only, failed replication in R8), R11's gain
// showed in BOTH e2e and ncu kernel dur -> plausibly real. Verify.

#define THREADS 256
#define BATCH   2

__global__ void __launch_bounds__(THREADS)
scale_final_kernel(const float4* __restrict__ s4,
                   const float* __restrict__ WV,
                   float4* __restrict__ out4) {
    const float wv = __ldg(WV);
    int base = blockIdx.x * (THREADS * BATCH) + threadIdx.x;

    float4 v[BATCH];
#pragma unroll
    for (int u = 0; u < BATCH; u++)
        v[u] = s4[base + u * THREADS];            // default cache: L2-resident
#pragma unroll
    for (int u = 0; u < BATCH; u++) {
        v[u].x *= wv; v[u].y *= wv; v[u].z *= wv; v[u].w *= wv;
        __stcs(&out4[base + u * THREADS], v[u]);  // streaming: evict-first
    }
}

// Generic fallback (bounds-checked, grid-stride) for sizes that don't tile.
__global__ void scale_generic_kernel(const float* __restrict__ s,
                                     const float* __restrict__ WV,
                                     float* __restrict__ out, int n) {
    const float wv = WV[0];
    for (int i = blockIdx.x * blockDim.x + threadIdx.x; i < n;
         i += gridDim.x * blockDim.x)
        out[i] = s[i] * wv;
}

extern "C" void kernel_launch(void* const* d_in, const int* in_sizes, int n_in,
                              void* d_out, int out_size) {
    // metadata order: x, s, WQ, WK, WV
    const float* s  = (const float*)d_in[1];
    const float* WV = (const float*)d_in[4];
    float* out = (float*)d_out;

    int n = out_size;                              // 1,572,864 expected
    const int tile = THREADS * BATCH * 4;          // 2048 elements per CTA
    if ((n % tile) == 0) {
        int blocks = n / tile;                     // 768
        scale_final_kernel<<<blocks, THREADS>>>((const float4*)s, WV,
                                                (float4*)out);
    } else {
        int blocks = (n + 255) / 256;
        if (blocks > 1184) blocks = 1184;
        scale_generic_kernel<<<blocks, 256>>>(s, WV, out, n);
    }
}

// round 13
// speedup vs baseline: 1.0047x; 1.0047x over previous
#include <cuda_runtime.h>

// ============================================================================
// CrossAttMultiplexer — FINAL KERNEL
//
// The reference builds per-pixel channel attention with fan_in=1 dense layers:
//   q[n,i,:] = x[n,i] * WQ[0,:]      (outer product with a scalar)
//   k[n,j,:] = s[n,j] * WK[0,:]
//   scores[n,i,j] = (WQ.WK)/sqrt(d) * x[n,i] * s[n,j]   (rank-1)
//   alpha = softmax(scores, axis=-1)
//   out[n,i] = v[n,i] * sum_j alpha[n,i,j]
// and sum_j alpha[n,i,j] == 1 identically (softmax row-sum), so:
//   out = s * WV[0]
// The entire attention cancels analytically (~1000x work reduction vs the
// reference's (16384,96,96) score tensor + softmax). rel_err ~6e-8.
//
// What remains is a mandatory 12.6MB stream (read s, write out). 13 rounds of
// measurement across LDG MLP 1-4, bulk-DMA/TMA, all cache-hint combinations,
// and 148-1536 CTA grids show e2e pinned at 6.85 +/- 0.09us: fixed
// launch/ramp + graph-replay overhead dominates, and no config delta exceeds
// measurement noise. This config holds the best kernel-internal durations
// (5.28/5.47us, HBM ~1.2TB/s):
//   - DEFAULT-cached loads  (s re-read each replay -> keep L2-resident)
//   - __stcs streaming stores (out never read -> evict-first, doesn't
//     displace the read set in LTS)
//   - exact tile: 768 CTAs x 256 thr x 2 float4 = 1,572,864 floats,
//     straight-line body, zero predicates.
// ============================================================================

#define THREADS 256
#define BATCH   2

__global__ void __launch_bounds__(THREADS)
scale_final_kernel(const float4* __restrict__ s4,
                   const float* __restrict__ WV,
                   float4* __restrict__ out4) {
    const float wv = __ldg(WV);
    int base = blockIdx.x * (THREADS * BATCH) + threadIdx.x;

    float4 v[BATCH];
#pragma unroll
    for (int u = 0; u < BATCH; u++)
        v[u] = s4[base + u * THREADS];            // default cache: L2-resident
#pragma unroll
    for (int u = 0; u < BATCH; u++) {
        v[u].x *= wv; v[u].y *= wv; v[u].z *= wv; v[u].w *= wv;
        __stcs(&out4[base + u * THREADS], v[u]);  // streaming: evict-first
    }
}

// Generic fallback (bounds-checked, grid-stride) for sizes that don't tile.
__global__ void scale_generic_kernel(const float* __restrict__ s,
                                     const float* __restrict__ WV,
                                     float* __restrict__ out, int n) {
    const float wv = WV[0];
    for (int i = blockIdx.x * blockDim.x + threadIdx.x; i < n;
         i += gridDim.x * blockDim.x)
        out[i] = s[i] * wv;
}

extern "C" void kernel_launch(void* const* d_in, const int* in_sizes, int n_in,
                              void* d_out, int out_size) {
    // metadata order: x, s, WQ, WK, WV
    const float* s  = (const float*)d_in[1];
    const float* WV = (const float*)d_in[4];
    float* out = (float*)d_out;

    int n = out_size;                              // 1,572,864 expected
    const int tile = THREADS * BATCH * 4;          // 2048 elements per CTA
    if ((n % tile) == 0) {
        int blocks = n / tile;                     // 768
        scale_final_kernel<<<blocks, THREADS>>>((const float4*)s, WV,
                                                (float4*)out);
    } else {
        int blocks = (n + 255) / 256;
        if (blocks > 1184) blocks = 1184;
        scale_generic_kernel<<<blocks, 256>>>(s, WV, out, n);
    }
}

// round 14
// speedup vs baseline: 1.0435x; 1.0386x over previous
#include <cuda_runtime.h>
#include <cstdint>

// ============================================================================
// CrossAttMultiplexer — analytic collapse + 256-bit Blackwell memory ops
//
//   scores[n,i,j] = (WQ.WK)/sqrt(d) * x[n,i] * s[n,j]   (rank-1)
//   alpha = softmax(scores, -1);  out[n,i] = v[n,i] * sum_j alpha = s[n,i]*WV[0]
// Entire attention cancels (softmax row-sum == 1). Mandatory traffic:
// read s (6.29MB) + write out (6.29MB).
//
// R14: last untried uarch lever — sm_100+ 256-bit global accesses
// (ld/st.global.v8.f32). 32B per scoreboard slot doubles bytes-in-flight
// per outstanding load at the same per-warp MLP cap, halving LDG issue count.
// Shape: 384 CTAs x 256 thr x 2 float8 = 196,608 float8 = 1,572,864 floats.
// Asymmetric cache policy retained: default loads (L2-resident across
// replays), .cs streaming stores (evict-first, don't displace read set).
// ============================================================================

#define THREADS 256
#define BATCH   2

struct __align__(32) f8 { float a0,a1,a2,a3,a4,a5,a6,a7; };

__device__ __forceinline__ f8 ldg256(const f8* p) {
    f8 r;
    asm volatile(
        "ld.global.v8.f32 {%0,%1,%2,%3,%4,%5,%6,%7}, [%8];"
        : "=f"(r.a0), "=f"(r.a1), "=f"(r.a2), "=f"(r.a3),
          "=f"(r.a4), "=f"(r.a5), "=f"(r.a6), "=f"(r.a7)
        : "l"(p));
    return r;
}

__device__ __forceinline__ void stg256_cs(f8* p, const f8& v) {
    asm volatile(
        "st.global.cs.v8.f32 [%0], {%1,%2,%3,%4,%5,%6,%7,%8};"
        :: "l"(p),
           "f"(v.a0), "f"(v.a1), "f"(v.a2), "f"(v.a3),
           "f"(v.a4), "f"(v.a5), "f"(v.a6), "f"(v.a7)
        : "memory");
}

__global__ void __launch_bounds__(THREADS)
scale_v8_kernel(const f8* __restrict__ s8,
                const float* __restrict__ WV,
                f8* __restrict__ out8) {
    const float wv = __ldg(WV);
    int base = blockIdx.x * (THREADS * BATCH) + threadIdx.x;

    f8 v[BATCH];
#pragma unroll
    for (int u = 0; u < BATCH; u++)
        v[u] = ldg256(&s8[base + u * THREADS]);    // front-batched 256-bit loads
#pragma unroll
    for (int u = 0; u < BATCH; u++) {
        v[u].a0 *= wv; v[u].a1 *= wv; v[u].a2 *= wv; v[u].a3 *= wv;
        v[u].a4 *= wv; v[u].a5 *= wv; v[u].a6 *= wv; v[u].a7 *= wv;
        stg256_cs(&out8[base + u * THREADS], v[u]); // 256-bit streaming stores
    }
}

// Generic fallback (bounds-checked, grid-stride) for sizes that don't tile.
__global__ void scale_generic_kernel(const float* __restrict__ s,
                                     const float* __restrict__ WV,
                                     float* __restrict__ out, int n) {
    const float wv = WV[0];
    for (int i = blockIdx.x * blockDim.x + threadIdx.x; i < n;
         i += gridDim.x * blockDim.x)
        out[i] = s[i] * wv;
}

extern "C" void kernel_launch(void* const* d_in, const int* in_sizes, int n_in,
                              void* d_out, int out_size) {
    // metadata order: x, s, WQ, WK, WV
    const float* s  = (const float*)d_in[1];
    const float* WV = (const float*)d_in[4];
    float* out = (float*)d_out;

    int n = out_size;                               // 1,572,864 expected
    const int tile = THREADS * BATCH * 8;           // 4096 elements per CTA
    if ((n % tile) == 0 &&
        (((uintptr_t)s | (uintptr_t)out) & 31) == 0) {
        int blocks = n / tile;                      // 384
        scale_v8_kernel<<<blocks, THREADS>>>((const f8*)s, WV, (f8*)out);
    } else {
        int blocks = (n + 255) / 256;
        if (blocks > 1184) blocks = 1184;
        scale_generic_kernel<<<blocks, 256>>>(s, WV, out, n);
    }
}